// round 1
// baseline (speedup 1.0000x reference)
#include <cuda_runtime.h>
#include <cstdint>

#define N_NODES 50000
#define D 128
#define N_EDGES 625000

// Scratch (allocation-free rule: device globals)
__device__ float g_sum[N_NODES * D];   // 25.6 MB
__device__ float g_deg[N_NODES];
__device__ float g_inv[N_NODES];

// ---------------------------------------------------------------------------
// Kernel 1: zero the accumulators (graph is replayed; must re-zero each run)
// ---------------------------------------------------------------------------
__global__ void zero_kernel() {
    int tid = blockIdx.x * blockDim.x + threadIdx.x;
    const int tot4 = (N_NODES * D) / 4;
    float4 z = make_float4(0.f, 0.f, 0.f, 0.f);
    float4* s4 = reinterpret_cast<float4*>(g_sum);
    for (int i = tid; i < tot4; i += gridDim.x * blockDim.x) s4[i] = z;
    if (tid < N_NODES) g_deg[tid] = 0.f;
}

// ---------------------------------------------------------------------------
// Kernel 2: edge scatter. One warp per edge: 32 lanes x float4 = 128 floats.
// red.global.add.v4.f32 -> one 16B L2 reduction per lane (4x fewer atomic ops
// than scalar atomicAdd).
// ---------------------------------------------------------------------------
__global__ void scatter_kernel(const float* __restrict__ x,
                               const int* __restrict__ ei) {
    int warp = (blockIdx.x * blockDim.x + threadIdx.x) >> 5;
    int lane = threadIdx.x & 31;
    if (warp >= N_EDGES) return;
    int src = ei[warp];
    int dst = ei[N_EDGES + warp];

    const float4* xr = reinterpret_cast<const float4*>(x + (size_t)src * D);
    float4 v = xr[lane];
    float* dptr = g_sum + (size_t)dst * D + lane * 4;
    asm volatile("red.global.add.v4.f32 [%0], {%1, %2, %3, %4};"
                 :: "l"(dptr), "f"(v.x), "f"(v.y), "f"(v.z), "f"(v.w)
                 : "memory");
    if (lane == 0) atomicAdd(g_deg + dst, 1.0f);
}

// ---------------------------------------------------------------------------
// Kernel 3: inverse degree (exact IEEE divide, trivially cheap)
// ---------------------------------------------------------------------------
__global__ void inv_kernel() {
    int i = blockIdx.x * blockDim.x + threadIdx.x;
    if (i < N_NODES) g_inv[i] = 1.0f / fmaxf(g_deg[i], 1.0f);
}

// ---------------------------------------------------------------------------
// Kernel 4: fused GEMM epilogue:
//   out = x + relu( (sum*inv) @ W_l + b_l + x @ W_r )
// W_l, W_r resident in smem. 128 rows/block, thread = 8 rows x 8 cols,
// f32x2 packed FMA over row pairs (transposed A tiles, stride 130 so pairs
// are 8B aligned -> natural LDS.64 f32x2 operands).
// ---------------------------------------------------------------------------
#define TM 128          // rows per block
#define KC 64           // k-chunk
#define SP 130          // padded transposed-tile stride (even -> 8B-aligned pairs)

__device__ __forceinline__ unsigned long long ffma2(unsigned long long a,
                                                    unsigned long long b,
                                                    unsigned long long c) {
    unsigned long long d;
    asm("fma.rn.f32x2 %0, %1, %2, %3;" : "=l"(d) : "l"(a), "l"(b), "l"(c));
    return d;
}
__device__ __forceinline__ unsigned long long pack2(float w) {
    unsigned long long d;
    asm("mov.b64 %0, {%1, %1};" : "=l"(d) : "f"(w));
    return d;
}
__device__ __forceinline__ void unpack2(unsigned long long v, float& lo, float& hi) {
    asm("mov.b64 {%0, %1}, %2;" : "=f"(lo), "=f"(hi) : "l"(v));
}

extern __shared__ float smem[];

__global__ __launch_bounds__(256, 1)
void gemm_kernel(const float* __restrict__ x,
                 const float* __restrict__ Wl,
                 const float* __restrict__ bl,
                 const float* __restrict__ Wr,
                 float* __restrict__ out) {
    float* sWl = smem;                       // 128*128
    float* sWr = smem + 16384;               // 128*128
    float* sB  = smem + 32768;               // 128
    float* sM  = smem + 32768 + 128;         // KC*SP (transposed mean chunk)
    float* sX  = sM + KC * SP;               // KC*SP (transposed x chunk)

    const int tid = threadIdx.x;

    // Stage weights (fp32, 128KB total) into smem
    #pragma unroll
    for (int i = 0; i < 16; i++) {
        int idx = tid + i * 256;
        reinterpret_cast<float4*>(sWl)[idx] = reinterpret_cast<const float4*>(Wl)[idx];
        reinterpret_cast<float4*>(sWr)[idx] = reinterpret_cast<const float4*>(Wr)[idx];
    }
    if (tid < 128) sB[tid] = bl[tid];

    const int m0 = blockIdx.x * TM;
    const int cg = tid & 15;        // 16 col groups of 8
    const int rg = tid >> 4;        // 16 row groups of 8
    const int r0 = rg * 8;
    const int c0 = cg * 8;

    unsigned long long acc[8][4];
    #pragma unroll
    for (int j = 0; j < 8; j++)
        #pragma unroll
        for (int p = 0; p < 4; p++) acc[j][p] = 0ull;

    for (int c = 0; c < D / KC; c++) {
        const int kb = c * KC;
        __syncthreads();
        // Load + transpose tiles: A_t[k][r], mean scaled by inv-degree.
        #pragma unroll
        for (int it = 0; it < 8; it++) {
            int f   = tid + it * 256;    // 0..2047
            int r   = f >> 4;            // 0..127
            int kq  = f & 15;            // 0..15 (float4 within chunk)
            int row = m0 + r;
            float4 mv = make_float4(0.f, 0.f, 0.f, 0.f);
            float4 xv = mv;
            if (row < N_NODES) {
                float id = g_inv[row];
                float4 s4 = *reinterpret_cast<const float4*>(g_sum + (size_t)row * D + kb + kq * 4);
                mv.x = s4.x * id; mv.y = s4.y * id; mv.z = s4.z * id; mv.w = s4.w * id;
                xv = *reinterpret_cast<const float4*>(x + (size_t)row * D + kb + kq * 4);
            }
            int kk = kq * 4;
            sM[(kk + 0) * SP + r] = mv.x;
            sM[(kk + 1) * SP + r] = mv.y;
            sM[(kk + 2) * SP + r] = mv.z;
            sM[(kk + 3) * SP + r] = mv.w;
            sX[(kk + 0) * SP + r] = xv.x;
            sX[(kk + 1) * SP + r] = xv.y;
            sX[(kk + 2) * SP + r] = xv.z;
            sX[(kk + 3) * SP + r] = xv.w;
        }
        __syncthreads();

        #pragma unroll 4
        for (int k = 0; k < KC; k++) {
            const float* mp = sM + k * SP + r0;
            const float* xp = sX + k * SP + r0;
            unsigned long long mm[4], xx[4];
            #pragma unroll
            for (int p = 0; p < 4; p++) {
                mm[p] = *reinterpret_cast<const unsigned long long*>(mp + 2 * p);
                xx[p] = *reinterpret_cast<const unsigned long long*>(xp + 2 * p);
            }
            const float* wlp = sWl + (kb + k) * D + c0;
            const float* wrp = sWr + (kb + k) * D + c0;
            float4 wl0 = *reinterpret_cast<const float4*>(wlp);
            float4 wl1 = *reinterpret_cast<const float4*>(wlp + 4);
            float4 wr0 = *reinterpret_cast<const float4*>(wrp);
            float4 wr1 = *reinterpret_cast<const float4*>(wrp + 4);
            float wls[8] = {wl0.x, wl0.y, wl0.z, wl0.w, wl1.x, wl1.y, wl1.z, wl1.w};
            float wrs[8] = {wr0.x, wr0.y, wr0.z, wr0.w, wr1.x, wr1.y, wr1.z, wr1.w};
            #pragma unroll
            for (int j = 0; j < 8; j++) {
                unsigned long long wp = pack2(wls[j]);
                #pragma unroll
                for (int p = 0; p < 4; p++) acc[j][p] = ffma2(mm[p], wp, acc[j][p]);
                unsigned long long wq = pack2(wrs[j]);
                #pragma unroll
                for (int p = 0; p < 4; p++) acc[j][p] = ffma2(xx[p], wq, acc[j][p]);
            }
        }
    }

    // Epilogue: out = x + relu(acc + b)
    #pragma unroll
    for (int p = 0; p < 4; p++) {
        #pragma unroll
        for (int lo = 0; lo < 2; lo++) {
            int row = m0 + r0 + 2 * p + lo;
            if (row < N_NODES) {
                float vals[8];
                #pragma unroll
                for (int j = 0; j < 8; j++) {
                    float a, b;
                    unpack2(acc[j][p], a, b);
                    float g = lo ? b : a;
                    g += sB[c0 + j];
                    vals[j] = fmaxf(g, 0.f);
                }
                const float4* xr = reinterpret_cast<const float4*>(x + (size_t)row * D + c0);
                float4 x0 = xr[0], x1 = xr[1];
                float4 o0 = make_float4(vals[0] + x0.x, vals[1] + x0.y,
                                        vals[2] + x0.z, vals[3] + x0.w);
                float4 o1 = make_float4(vals[4] + x1.x, vals[5] + x1.y,
                                        vals[6] + x1.z, vals[7] + x1.w);
                float4* orow = reinterpret_cast<float4*>(out + (size_t)row * D + c0);
                orow[0] = o0;
                orow[1] = o1;
            }
        }
    }
}

// ---------------------------------------------------------------------------
// launch
// ---------------------------------------------------------------------------
extern "C" void kernel_launch(void* const* d_in, const int* in_sizes, int n_in,
                              void* d_out, int out_size) {
    const float* x  = (const float*)d_in[0];
    const int*   ei = (const int*)d_in[1];
    const float* Wl = (const float*)d_in[2];
    const float* bl = (const float*)d_in[3];
    const float* Wr = (const float*)d_in[4];
    float* out = (float*)d_out;

    (void)in_sizes; (void)n_in; (void)out_size;

    // 1. zero accumulators
    zero_kernel<<<1600, 256>>>();

    // 2. scatter (1 warp per edge)
    {
        int warps = N_EDGES;
        int blocks = (warps * 32 + 255) / 256;
        scatter_kernel<<<blocks, 256>>>(x, ei);
    }

    // 3. inverse degree
    inv_kernel<<<(N_NODES + 255) / 256, 256>>>();

    // 4. fused dual-GEMM + bias + relu + residual
    {
        size_t smem_bytes = (size_t)(16384 * 2 + 128 + 2 * KC * SP) * sizeof(float);
        cudaFuncSetAttribute(gemm_kernel,
                             cudaFuncAttributeMaxDynamicSharedMemorySize,
                             (int)smem_bytes);
        int blocks = (N_NODES + TM - 1) / TM;   // 391
        gemm_kernel<<<blocks, 256, smem_bytes>>>(x, Wl, bl, Wr, out);
    }
}

// round 4
// speedup vs baseline: 1.2541x; 1.2541x over previous
#include <cuda_runtime.h>
#include <cuda_bf16.h>
#include <cstdint>

#define N_NODES 50000
#define D 128
#define N_EDGES 625000

// Scratch (allocation-free rule: device globals; BSS zero-initialized)
__device__ float g_sum[N_NODES * D];          // re-zeroed by gemm each run
__device__ float g_deg[N_NODES];              // re-zeroed by inv each run
__device__ float g_inv[N_NODES];
__device__ __nv_bfloat16 g_W[4 * 128 * 128];  // [mat][k][n]: Wl_hi, Wl_lo, Wr_hi, Wr_lo

// ---------------------------------------------------------------------------
// helpers
// ---------------------------------------------------------------------------
__device__ __forceinline__ uint32_t smem_u32(const void* p) {
    uint32_t a;
    asm("{ .reg .u64 t; cvta.to.shared.u64 t, %1; cvt.u32.u64 %0, t; }" : "=r"(a) : "l"(p));
    return a;
}

#define LDSM_X4(r, addr) \
    asm volatile("ldmatrix.sync.aligned.m8n8.x4.shared.b16 {%0,%1,%2,%3}, [%4];" \
                 : "=r"((r)[0]), "=r"((r)[1]), "=r"((r)[2]), "=r"((r)[3]) : "r"(addr))

#define LDSM_X4T(r, addr) \
    asm volatile("ldmatrix.sync.aligned.m8n8.x4.trans.shared.b16 {%0,%1,%2,%3}, [%4];" \
                 : "=r"((r)[0]), "=r"((r)[1]), "=r"((r)[2]), "=r"((r)[3]) : "r"(addr))

__device__ __forceinline__ void mma16816(float* d, const uint32_t* a, const uint32_t* b) {
    asm volatile(
        "mma.sync.aligned.m16n8k16.row.col.f32.bf16.bf16.f32 "
        "{%0,%1,%2,%3}, {%4,%5,%6,%7}, {%8,%9}, {%0,%1,%2,%3};"
        : "+f"(d[0]), "+f"(d[1]), "+f"(d[2]), "+f"(d[3])
        : "r"(a[0]), "r"(a[1]), "r"(a[2]), "r"(a[3]), "r"(b[0]), "r"(b[1]));
}

// ---------------------------------------------------------------------------
// Kernel: prep weights — hi/lo bf16 split, plain [mat][k][n] row-major
// ---------------------------------------------------------------------------
__global__ void prep_weights(const float* __restrict__ Wl,
                             const float* __restrict__ Wr) {
    int idx = blockIdx.x * blockDim.x + threadIdx.x;
    if (idx >= 2 * 128 * 128) return;
    int m2 = idx >> 14;           // 0 = Wl, 1 = Wr
    int k  = (idx >> 7) & 127;
    int n  = idx & 127;
    float w = (m2 ? Wr : Wl)[k * 128 + n];
    __nv_bfloat16 h = __float2bfloat16(w);
    __nv_bfloat16 l = __float2bfloat16(w - __bfloat162float(h));
    g_W[(m2 * 2 + 0) * 16384 + k * 128 + n] = h;
    g_W[(m2 * 2 + 1) * 16384 + k * 128 + n] = l;
}

// ---------------------------------------------------------------------------
// Kernel: edge scatter. One warp per edge, red.global.add.v4.f32.
// ---------------------------------------------------------------------------
__global__ void scatter_kernel(const float* __restrict__ x,
                               const int* __restrict__ ei) {
    int warp = (blockIdx.x * blockDim.x + threadIdx.x) >> 5;
    int lane = threadIdx.x & 31;
    if (warp >= N_EDGES) return;
    int src = ei[warp];
    int dst = ei[N_EDGES + warp];
    const float4* xr = reinterpret_cast<const float4*>(x + (size_t)src * D);
    float4 v = xr[lane];
    float* dptr = g_sum + (size_t)dst * D + lane * 4;
    asm volatile("red.global.add.v4.f32 [%0], {%1, %2, %3, %4};"
                 :: "l"(dptr), "f"(v.x), "f"(v.y), "f"(v.z), "f"(v.w)
                 : "memory");
    if (lane == 0) atomicAdd(g_deg + dst, 1.0f);
}

// ---------------------------------------------------------------------------
// Kernel: inverse degree; re-zeroes g_deg for the next replay
// ---------------------------------------------------------------------------
__global__ void inv_kernel() {
    int i = blockIdx.x * blockDim.x + threadIdx.x;
    if (i < N_NODES) {
        float d = g_deg[i];
        g_inv[i] = 1.0f / fmaxf(d, 1.0f);
        g_deg[i] = 0.0f;
    }
}

// ---------------------------------------------------------------------------
// Kernel: HMMA GEMM: out = x + relu([mean|x] @ [Wl;Wr] + b)
// bf16 hi/lo 3-term compensation. 128x128 tile/CTA, 8 warps, m16n8k16 mma.
// SMEM: A mats (mhi,mlo,xhi,xlo) 128x64 bf16 stride 72; B mats 64x128 stride 136.
// ---------------------------------------------------------------------------
#define ASTR 72                     // bf16 elems per A row (144 B)
#define BSTR 136                    // bf16 elems per B row (272 B)
#define A_MAT_B (128 * ASTR * 2)    // 18432 B
#define B_MAT_B (64 * BSTR * 2)     // 17408 B
#define SM_A_B (4 * A_MAT_B)        // 73728 B
#define SM_B_B (4 * B_MAT_B)        // 69632 B
#define SMEM_TOTAL (SM_A_B + SM_B_B)

__global__ __launch_bounds__(256, 1)
void gemm_mma(const float* __restrict__ x,
              const float* __restrict__ bl,
              float* __restrict__ out) {
    extern __shared__ char sm[];
    const uint32_t sA = smem_u32(sm);
    const uint32_t sB = sA + SM_A_B;

    const int tid = threadIdx.x;
    const int lane = tid & 31;
    const int w = tid >> 5;
    const int wg = tid >> 7;        // 0: mean path, 1: x path (conversion)
    const int wrow = tid & 127;
    const int m0 = blockIdx.x * 128;
    const int mrow0 = (w >> 1) * 32;
    const int ncol0 = (w & 1) * 64;

    float acc[2][8][4];
    #pragma unroll
    for (int mt = 0; mt < 2; mt++)
        #pragma unroll
        for (int nt = 0; nt < 8; nt++)
            #pragma unroll
            for (int q = 0; q < 4; q++) acc[mt][nt][q] = 0.f;

    for (int c = 0; c < 2; c++) {
        const int k0 = c * 64;
        __syncthreads();   // previous MMA done before smem overwrite

        // ---- A conversion: one row per thread, 64-col chunk -> hi/lo bf16 ----
        {
            int row = m0 + wrow;
            bool valid = row < N_NODES;
            const float* src = wg ? (x + (size_t)row * D + k0)
                                  : (g_sum + (size_t)row * D + k0);
            float s = 1.0f;
            if (!wg && valid) s = g_inv[row];

            uint32_t hi[32], lo[32];
            #pragma unroll
            for (int i = 0; i < 16; i++) {
                float4 v = valid ? reinterpret_cast<const float4*>(src)[i]
                                 : make_float4(0.f, 0.f, 0.f, 0.f);
                float e0 = v.x * s, e1 = v.y * s, e2 = v.z * s, e3 = v.w * s;
                __nv_bfloat16 h0 = __float2bfloat16(e0), h1 = __float2bfloat16(e1);
                __nv_bfloat16 h2 = __float2bfloat16(e2), h3 = __float2bfloat16(e3);
                __nv_bfloat16 l0 = __float2bfloat16(e0 - __bfloat162float(h0));
                __nv_bfloat16 l1 = __float2bfloat16(e1 - __bfloat162float(h1));
                __nv_bfloat16 l2 = __float2bfloat16(e2 - __bfloat162float(h2));
                __nv_bfloat16 l3 = __float2bfloat16(e3 - __bfloat162float(h3));
                hi[2*i]   = (uint32_t)__bfloat16_as_ushort(h0) | ((uint32_t)__bfloat16_as_ushort(h1) << 16);
                hi[2*i+1] = (uint32_t)__bfloat16_as_ushort(h2) | ((uint32_t)__bfloat16_as_ushort(h3) << 16);
                lo[2*i]   = (uint32_t)__bfloat16_as_ushort(l0) | ((uint32_t)__bfloat16_as_ushort(l1) << 16);
                lo[2*i+1] = (uint32_t)__bfloat16_as_ushort(l2) | ((uint32_t)__bfloat16_as_ushort(l3) << 16);
            }
            uint4* dh = reinterpret_cast<uint4*>(sm + (wg * 2 + 0) * A_MAT_B + wrow * (ASTR * 2));
            uint4* dl = reinterpret_cast<uint4*>(sm + (wg * 2 + 1) * A_MAT_B + wrow * (ASTR * 2));
            #pragma unroll
            for (int i = 0; i < 8; i++) {
                dh[i] = make_uint4(hi[4*i], hi[4*i+1], hi[4*i+2], hi[4*i+3]);
                dl[i] = make_uint4(lo[4*i], lo[4*i+1], lo[4*i+2], lo[4*i+3]);
            }
            // re-zero g_sum chunk for next graph replay (after it has been read)
            if (!wg && valid) {
                float4* z = reinterpret_cast<float4*>(g_sum + (size_t)row * D + k0);
                float4 zz = make_float4(0.f, 0.f, 0.f, 0.f);
                #pragma unroll
                for (int i = 0; i < 16; i++) z[i] = zz;
            }
        }

        // ---- B copy: 4 mats x 64 rows x 128 cols bf16 into padded smem ----
        #pragma unroll
        for (int i = 0; i < 16; i++) {
            int idx = tid + i * 256;           // 0..4095
            int mat = idx >> 10;
            int rem = idx & 1023;
            int r = rem >> 4, sg = rem & 15;
            uint4 v = *reinterpret_cast<const uint4*>(g_W + mat * 16384 + (k0 + r) * 128 + sg * 8);
            *reinterpret_cast<uint4*>(sm + SM_A_B + mat * B_MAT_B + r * (BSTR * 2) + sg * 16) = v;
        }
        __syncthreads();

        // ---- MMA mainloop: 4 k16-steps ----
        #pragma unroll
        for (int ks = 0; ks < 4; ks++) {
            const int kk = ks * 16;
            uint32_t a[4][2][4];
            #pragma unroll
            for (int mat = 0; mat < 4; mat++)
                #pragma unroll
                for (int mt = 0; mt < 2; mt++) {
                    uint32_t addr = sA + mat * A_MAT_B
                                  + (mrow0 + mt * 16 + (lane & 15)) * (ASTR * 2)
                                  + (kk + ((lane >> 4) * 8)) * 2;
                    LDSM_X4(a[mat][mt], addr);
                }
            #pragma unroll
            for (int np = 0; np < 4; np++) {
                const int ncol = ncol0 + np * 16;
                uint32_t b[4][4];
                #pragma unroll
                for (int mat = 0; mat < 4; mat++) {
                    int quad = lane >> 3;
                    uint32_t addr = sB + mat * B_MAT_B
                                  + (kk + (quad & 1) * 8 + (lane & 7)) * (BSTR * 2)
                                  + (ncol + (quad >> 1) * 8) * 2;
                    LDSM_X4T(b[mat], addr);
                }
                #pragma unroll
                for (int mt = 0; mt < 2; mt++)
                    #pragma unroll
                    for (int nt = 0; nt < 2; nt++) {
                        float* d = acc[mt][np * 2 + nt];
                        mma16816(d, a[0][mt], b[0] + nt * 2);   // m_hi * Wl_hi
                        mma16816(d, a[1][mt], b[0] + nt * 2);   // m_lo * Wl_hi
                        mma16816(d, a[0][mt], b[1] + nt * 2);   // m_hi * Wl_lo
                        mma16816(d, a[2][mt], b[2] + nt * 2);   // x_hi * Wr_hi
                        mma16816(d, a[3][mt], b[2] + nt * 2);   // x_lo * Wr_hi
                        mma16816(d, a[2][mt], b[3] + nt * 2);   // x_hi * Wr_lo
                    }
            }
        }
    }

    // ---- epilogue: out = x + relu(acc + b) ----
    const int rq = lane >> 2;
    const int cq = (lane & 3) * 2;
    #pragma unroll
    for (int mt = 0; mt < 2; mt++)
        #pragma unroll
        for (int h = 0; h < 2; h++) {
            int row = m0 + mrow0 + mt * 16 + h * 8 + rq;
            if (row < N_NODES) {
                #pragma unroll
                for (int nt = 0; nt < 8; nt++) {
                    int col = ncol0 + nt * 8 + cq;
                    float d0 = acc[mt][nt][h * 2 + 0];
                    float d1 = acc[mt][nt][h * 2 + 1];
                    float2 bv = *reinterpret_cast<const float2*>(bl + col);
                    float2 xv = *reinterpret_cast<const float2*>(x + (size_t)row * D + col);
                    float2 o;
                    o.x = xv.x + fmaxf(d0 + bv.x, 0.f);
                    o.y = xv.y + fmaxf(d1 + bv.y, 0.f);
                    *reinterpret_cast<float2*>(out + (size_t)row * D + col) = o;
                }
            }
        }
}

// ---------------------------------------------------------------------------
// launch
// ---------------------------------------------------------------------------
extern "C" void kernel_launch(void* const* d_in, const int* in_sizes, int n_in,
                              void* d_out, int out_size) {
    const float* x  = (const float*)d_in[0];
    const int*   ei = (const int*)d_in[1];
    const float* Wl = (const float*)d_in[2];
    const float* bl = (const float*)d_in[3];
    const float* Wr = (const float*)d_in[4];
    float* out = (float*)d_out;
    (void)in_sizes; (void)n_in; (void)out_size;

    // 1. weight prep (hi/lo bf16 split)
    prep_weights<<<(2 * 128 * 128 + 255) / 256, 256>>>(Wl, Wr);

    // 2. edge scatter (1 warp per edge; g_sum zeroed by previous gemm / BSS init)
    scatter_kernel<<<(N_EDGES * 32 + 255) / 256, 256>>>(x, ei);

    // 3. inverse degree (re-zeroes g_deg)
    inv_kernel<<<(N_NODES + 255) / 256, 256>>>();

    // 4. HMMA dual GEMM + bias + relu + residual (re-zeroes g_sum)
    {
        cudaFuncSetAttribute(gemm_mma, cudaFuncAttributeMaxDynamicSharedMemorySize,
                             SMEM_TOTAL);
        gemm_mma<<<(N_NODES + 127) / 128, 256, SMEM_TOTAL>>>(x, bl, out);
    }
}